// round 12
// baseline (speedup 1.0000x reference)
#include <cuda_runtime.h>
#include <cuda_fp16.h>

// LSTM_8615704395881: B=64, T=16384, I=1, H=32, O=1.
// Kernel 1 (recurrent): 1 CTA/batch, 128 threads (4 homogeneous warps).
//   lane = 4*j_local + gate ; warp w owns hidden units [8w, 8w+8).
//   Per step: LDS h -> 32-MAC dot (f32x2, two 8-deep chains; x/bias seed
//   hoisted) -> MUFU.TANH act (0.5 folded into weights for sigmoid
//   gates) -> 3 shuffles (g,i,f; writer lane g==3 owns o) -> redundant
//   cell update -> h STS to 32-deep SMEM ring -> barrier. h exported to
//   gmem in 16-step batches: cooperative ring->gmem fp16 copy (race-free
//   half-ring distance), replacing the per-step STG.16.
// Kernel 2 (head): out = x + h_dev @ W_lin + b_lin, 2 rows/thread.

#define BATCH 64
#define TLEN  16384
#define HID   32
#define NT    128
#define RING  32

typedef unsigned long long ull;
typedef unsigned int uint;

__device__ __align__(16) __half h_dev[(size_t)BATCH * TLEN * HID];  // 64 MB fp16 scratch

__device__ __forceinline__ float tanh_fast(float x) {
    float r; asm("tanh.approx.f32 %0, %1;" : "=f"(r) : "f"(x)); return r;
}
__device__ __forceinline__ ull fma2(ull a, ull b, ull c) {
    ull d; asm("fma.rn.f32x2 %0, %1, %2, %3;" : "=l"(d) : "l"(a), "l"(b), "l"(c));
    return d;
}
__device__ __forceinline__ ull add2(ull a, ull b) {
    ull d; asm("add.rn.f32x2 %0, %1, %2;" : "=l"(d) : "l"(a), "l"(b));
    return d;
}
__device__ __forceinline__ ull pack2(float x, float y) {
    ull v; asm("mov.b64 %0, {%1, %2};" : "=l"(v) : "f"(x), "f"(y)); return v;
}
__device__ __forceinline__ float2 unpack2(ull v) {
    float2 f; asm("mov.b64 {%0, %1}, %2;" : "=f"(f.x), "=f"(f.y) : "l"(v)); return f;
}

// one LSTM timestep; X0 = prepacked (x*wih + bias, 0) seed.
// HR/HW are compile-time ring-slot row pointers.
#define STEP(X0, HR, HW)                                                      \
    do {                                                                      \
        ull a0 = (X0);                                                        \
        ull a1 = 0ull;                                                        \
        _Pragma("unroll")                                                     \
        for (int i = 0; i < 4; i++) {                                         \
            ulonglong2 ha  = *(const ulonglong2*)((HR) + 8 * i);              \
            ulonglong2 hb2 = *(const ulonglong2*)((HR) + 8 * i + 4);          \
            a0 = fma2(w2[4 * i + 0], ha.x,  a0);                              \
            a1 = fma2(w2[4 * i + 1], ha.y,  a1);                              \
            a0 = fma2(w2[4 * i + 2], hb2.x, a0);                              \
            a1 = fma2(w2[4 * i + 3], hb2.y, a1);                              \
        }                                                                     \
        float2 sf = unpack2(add2(a0, a1));                                    \
        float act = fmaf(tanh_fast(sf.x + sf.y), sa, sb);                     \
        float gv = __shfl_sync(0xffffffffu, act, base4 + 2);                  \
        float iv = __shfl_sync(0xffffffffu, act, base4);                      \
        float fv = __shfl_sync(0xffffffffu, act, base4 + 1);                  \
        c = fmaf(fv, c, iv * gv);                                             \
        float hres = act * tanh_fast(c);   /* act == o on writer lane */      \
        if (writer) (HW)[j] = hres;                                           \
        __syncthreads();                                                      \
    } while (0)

// cooperative export of 16 ring rows [SB, SB+16) -> gmem rows [ROW, ROW+16).
// Each thread: 1 LDS.128 + 2 f16x2 packs + 1 STG.64 (coalesced 64B/8 lanes).
#define COPYBLK(SB, ROW)                                                      \
    do {                                                                      \
        float4 hv = *(const float4*)&hr[(SB) + ctrow][cjg];                   \
        __half2 p0 = __floats2half2_rn(hv.x, hv.y);                          \
        __half2 p1 = __floats2half2_rn(hv.z, hv.w);                          \
        uint2 st;                                                             \
        st.x = *reinterpret_cast<uint*>(&p0);                                 \
        st.y = *reinterpret_cast<uint*>(&p1);                                 \
        houts[((size_t)(ROW) + ctrow) * 8 + cj8] = st;                        \
    } while (0)

// 16-step half-block: slots SB..SB+15, first step reads slot PS.
#define HALF16(SB, PS, XA, XB, XC, XD)                                        \
    do {                                                                      \
        ull s0  = pack2(fmaf((XA).x, wih, bsum), 0.f);                        \
        ull s1  = pack2(fmaf((XA).y, wih, bsum), 0.f);                        \
        ull s2  = pack2(fmaf((XA).z, wih, bsum), 0.f);                        \
        ull s3  = pack2(fmaf((XA).w, wih, bsum), 0.f);                        \
        ull s4  = pack2(fmaf((XB).x, wih, bsum), 0.f);                        \
        ull s5  = pack2(fmaf((XB).y, wih, bsum), 0.f);                        \
        ull s6  = pack2(fmaf((XB).z, wih, bsum), 0.f);                        \
        ull s7  = pack2(fmaf((XB).w, wih, bsum), 0.f);                        \
        ull s8  = pack2(fmaf((XC).x, wih, bsum), 0.f);                        \
        ull s9  = pack2(fmaf((XC).y, wih, bsum), 0.f);                        \
        ull s10 = pack2(fmaf((XC).z, wih, bsum), 0.f);                        \
        ull s11 = pack2(fmaf((XC).w, wih, bsum), 0.f);                        \
        ull s12 = pack2(fmaf((XD).x, wih, bsum), 0.f);                        \
        ull s13 = pack2(fmaf((XD).y, wih, bsum), 0.f);                        \
        ull s14 = pack2(fmaf((XD).z, wih, bsum), 0.f);                        \
        ull s15 = pack2(fmaf((XD).w, wih, bsum), 0.f);                        \
        STEP(s0,  hr[PS],        hr[(SB) + 0]);                               \
        STEP(s1,  hr[(SB) + 0],  hr[(SB) + 1]);                               \
        STEP(s2,  hr[(SB) + 1],  hr[(SB) + 2]);                               \
        STEP(s3,  hr[(SB) + 2],  hr[(SB) + 3]);                               \
        STEP(s4,  hr[(SB) + 3],  hr[(SB) + 4]);                               \
        STEP(s5,  hr[(SB) + 4],  hr[(SB) + 5]);                               \
        STEP(s6,  hr[(SB) + 5],  hr[(SB) + 6]);                               \
        STEP(s7,  hr[(SB) + 6],  hr[(SB) + 7]);                               \
        STEP(s8,  hr[(SB) + 7],  hr[(SB) + 8]);                               \
        STEP(s9,  hr[(SB) + 8],  hr[(SB) + 9]);                               \
        STEP(s10, hr[(SB) + 9],  hr[(SB) + 10]);                              \
        STEP(s11, hr[(SB) + 10], hr[(SB) + 11]);                              \
        STEP(s12, hr[(SB) + 11], hr[(SB) + 12]);                              \
        STEP(s13, hr[(SB) + 12], hr[(SB) + 13]);                              \
        STEP(s14, hr[(SB) + 13], hr[(SB) + 14]);                              \
        STEP(s15, hr[(SB) + 14], hr[(SB) + 15]);                              \
    } while (0)

__global__ __launch_bounds__(NT, 1)
void lstm_rec(const float* __restrict__ x,
              const float* __restrict__ W_ih,
              const float* __restrict__ W_hh,
              const float* __restrict__ b_ih,
              const float* __restrict__ b_hh)
{
    __shared__ __align__(128) float hr[RING][HID];

    const int tid  = threadIdx.x;
    const int wid  = tid >> 5;
    const int lane = tid & 31;
    const int b    = blockIdx.x;

    const int g   = lane & 3;                  // gate: 0=i 1=f 2=g 3=o
    const int j   = (wid << 3) + (lane >> 2);  // hidden unit
    const int row = (g << 5) + j;

    // sigmoid(z) = 0.5*tanh(z/2)+0.5 : fold the /2 into the weights
    const float scale = (g == 2) ? 1.0f : 0.5f;
    const float sa    = (g == 2) ? 1.0f : 0.5f;
    const float sb    = (g == 2) ? 0.0f : 0.5f;

    ull w2[16];
    #pragma unroll
    for (int k = 0; k < 16; k++) {
        float wa = W_hh[row * HID + 2 * k]     * scale;
        float wb = W_hh[row * HID + 2 * k + 1] * scale;
        w2[k] = pack2(wa, wb);
    }
    const float wih  = W_ih[row] * scale;
    const float bsum = (b_ih[row] + b_hh[row]) * scale;
    const int base4  = lane & ~3;
    const bool writer = (g == 3);              // owns o -> no o-shuffle

    // export-copy constants
    uint2* houts     = (uint2*)(h_dev + (size_t)b * TLEN * HID);
    const int ctrow  = tid >> 3;               // ring row within half (0..15)
    const int cjg    = (tid & 7) << 2;         // float col (0,4,...,28)
    const int cj8    = tid & 7;                // uint2 col

    const float* xb = x + (size_t)b * TLEN;
    float c = 0.f;

    if (tid < HID) hr[RING - 1][tid] = 0.f;
    __syncthreads();

    // x for steps t..t+15 (c-regs) / t+16..t+31 (n-regs)
    float4 c0 = __ldg((const float4*)(xb + 0));
    float4 c1 = __ldg((const float4*)(xb + 4));
    float4 c2 = __ldg((const float4*)(xb + 8));
    float4 c3 = __ldg((const float4*)(xb + 12));

    for (int t = 0; t < TLEN; t += 32) {
        // export previous half-block (steps t-16..t-1, ring slots 16..31)
        if (t) COPYBLK(16, t - 16);

        // prefetch x for steps t+16..t+31
        float4 n0 = __ldg((const float4*)(xb + t + 16));
        float4 n1 = __ldg((const float4*)(xb + t + 20));
        float4 n2 = __ldg((const float4*)(xb + t + 24));
        float4 n3 = __ldg((const float4*)(xb + t + 28));

        HALF16(0, RING - 1, c0, c1, c2, c3);   // steps t..t+15 -> slots 0..15

        // export steps t..t+15 (slots 0..15) while half B runs on 16..31
        COPYBLK(0, t);

        // prefetch x for steps t+32..t+47 (wrap-masked on the last block)
        const int tn = (t + 32) & (TLEN - 1);
        c0 = __ldg((const float4*)(xb + tn));
        c1 = __ldg((const float4*)(xb + tn + 4));
        c2 = __ldg((const float4*)(xb + tn + 8));
        c3 = __ldg((const float4*)(xb + tn + 12));

        HALF16(16, 15, n0, n1, n2, n3);        // steps t+16..t+31 -> slots 16..31
    }
    // final export: steps TLEN-16..TLEN-1 (slots 16..31)
    COPYBLK(16, TLEN - 16);
}

// 2 rows per thread, direct (coalesced) loads, 8 independent LDG.128 in
// flight per thread. Row pair is (base+tid, base+256+tid).
__global__ __launch_bounds__(256, 4)
void lin_head(const float* __restrict__ x,
              const float* __restrict__ W_lin,
              const float* __restrict__ b_lin,
              float* __restrict__ out)
{
    const int tid = threadIdx.x;
    const size_t r0 = (size_t)blockIdx.x * 512 + tid;    // row 0
    const size_t r1 = r0 + 256;                          // row 1

    const uint4* h0p = (const uint4*)(h_dev + r0 * HID);
    const uint4* h1p = (const uint4*)(h_dev + r1 * HID);

    // issue all 8 row loads + 2 x loads up front (max MLP)
    uint4 u0 = h0p[0], u1 = h0p[1], u2 = h0p[2], u3 = h0p[3];
    uint4 v0 = h1p[0], v1 = h1p[1], v2 = h1p[2], v3 = h1p[3];
    float x0 = x[r0], x1 = x[r1];

    float w[32];
    #pragma unroll
    for (int k = 0; k < 8; k++) {
        float4 wv = __ldg((const float4*)W_lin + k);
        w[4*k] = wv.x; w[4*k+1] = wv.y; w[4*k+2] = wv.z; w[4*k+3] = wv.w;
    }
    const float bl = __ldg(b_lin);

    #define ROWACC(ACC, Q, WOFF)                                              \
        do {                                                                  \
            float2 f0 = __half22float2(*(const __half2*)&(Q).x);              \
            float2 f1 = __half22float2(*(const __half2*)&(Q).y);              \
            float2 f2 = __half22float2(*(const __half2*)&(Q).z);              \
            float2 f3 = __half22float2(*(const __half2*)&(Q).w);              \
            ACC = fmaf(f0.x, w[(WOFF)+0], fmaf(f0.y, w[(WOFF)+1], ACC));      \
            ACC = fmaf(f1.x, w[(WOFF)+2], fmaf(f1.y, w[(WOFF)+3], ACC));      \
            ACC = fmaf(f2.x, w[(WOFF)+4], fmaf(f2.y, w[(WOFF)+5], ACC));      \
            ACC = fmaf(f3.x, w[(WOFF)+6], fmaf(f3.y, w[(WOFF)+7], ACC));      \
        } while (0)

    float a0 = 0.f, a1 = 0.f;
    ROWACC(a0, u0,  0); ROWACC(a0, u1,  8); ROWACC(a0, u2, 16); ROWACC(a0, u3, 24);
    ROWACC(a1, v0,  0); ROWACC(a1, v1,  8); ROWACC(a1, v2, 16); ROWACC(a1, v3, 24);
    #undef ROWACC

    out[r0] = x0 + bl + a0;
    out[r1] = x1 + bl + a1;
}

extern "C" void kernel_launch(void* const* d_in, const int* in_sizes, int n_in,
                              void* d_out, int out_size) {
    lstm_rec<<<BATCH, NT>>>(
        (const float*)d_in[0],   // x
        (const float*)d_in[1],   // W_ih
        (const float*)d_in[2],   // W_hh
        (const float*)d_in[3],   // b_ih
        (const float*)d_in[4]);  // b_hh
    lin_head<<<(BATCH * TLEN) / 512, 256>>>(
        (const float*)d_in[0],   // x
        (const float*)d_in[5],   // W_lin
        (const float*)d_in[6],   // b_lin
        (float*)d_out);
}